// round 3
// baseline (speedup 1.0000x reference)
#include <cuda_runtime.h>
#include <cstdint>

// Dendrite_755914244697 — persistent 4-stage cp.async.bulk pipeline, sm_103a.
// out[o] = log( prod_{k<25} (1.1 + atan(10*(p[k]*w[o*25+k] - q[o*25+k]))/pi) )

#define IMG   128
#define OUTD  124
#define SIDE  5
#define SEG   25
#define TPB   128
#define TILE  128
#define NS    4
#define TILE_BYTES  (TILE * SEG * 4)          // 12800 B per array per tile
#define STAGE_BYTES (2 * TILE_BYTES)          // w + q = 25600 B
#define SMEM_BYTES  (128 + NS * STAGE_BYTES)  // 102528 B

__device__ __forceinline__ uint32_t smem_u32(const void* p)
{
    uint32_t a;
    asm("{ .reg .u64 t; cvta.to.shared.u64 t, %1; cvt.u32.u64 %0, t; }"
        : "=r"(a) : "l"(p));
    return a;
}

__device__ __forceinline__ void mbar_init(uint32_t mb, uint32_t count)
{
    asm volatile("mbarrier.init.shared.b64 [%0], %1;" :: "r"(mb), "r"(count) : "memory");
}

__device__ __forceinline__ void mbar_expect_tx(uint32_t mb, uint32_t bytes)
{
    asm volatile("mbarrier.arrive.expect_tx.shared.b64 _, [%0], %1;"
                 :: "r"(mb), "r"(bytes) : "memory");
}

__device__ __forceinline__ void bulk_g2s(uint32_t dst, const void* src,
                                         uint32_t bytes, uint32_t mb)
{
    asm volatile("cp.async.bulk.shared::cta.global.mbarrier::complete_tx::bytes "
                 "[%0], [%1], %2, [%3];"
                 :: "r"(dst), "l"(src), "r"(bytes), "r"(mb) : "memory");
}

__device__ __forceinline__ void mbar_wait(uint32_t mb, uint32_t phase)
{
    uint32_t done;
    asm volatile(
        "{ .reg .pred p;\n"
        "  mbarrier.try_wait.parity.acquire.cta.shared::cta.b64 p, [%1], %2;\n"
        "  selp.b32 %0, 1, 0, p; }"
        : "=r"(done) : "r"(mb), "r"(phase) : "memory");
    while (!done) {
        asm volatile(
            "{ .reg .pred p;\n"
            "  mbarrier.try_wait.parity.acquire.cta.shared::cta.b64 p, [%1], %2, 0x989680;\n"
            "  selp.b32 %0, 1, 0, p; }"
            : "=r"(done) : "r"(mb), "r"(phase) : "memory");
    }
}

// Signed-z atan: odd poly carries the sign; |u|>1 via atan(u)=copysign(pi/2,u)-atan(1/u).
__device__ __forceinline__ float fast_atan(float u)
{
    float inv;
    asm("rcp.approx.f32 %0, %1;" : "=f"(inv) : "f"(u));   // signed reciprocal
    bool  big = fabsf(u) > 1.0f;
    float z   = big ? inv : u;                             // signed arg, |z|<=1
    float s   = z * z;
    float p   =              -0.0040540580f;
    p = __fmaf_rn(p, s,  0.0218612288f);
    p = __fmaf_rn(p, s, -0.0559098861f);
    p = __fmaf_rn(p, s,  0.0964200441f);
    p = __fmaf_rn(p, s, -0.1390853351f);
    p = __fmaf_rn(p, s,  0.1994653599f);
    p = __fmaf_rn(p, s, -0.3332985605f);
    p = __fmaf_rn(p, s,  0.9999993329f);
    float r = p * z;                                       // sign-correct
    float c = __uint_as_float(0x3fc90fdbu |                // copysign(pi/2, u)
                              (__float_as_uint(u) & 0x80000000u));
    return big ? (c - r) : r;
}

__global__ void __launch_bounds__(TPB, 2)
dendrite_kernel(const float* __restrict__ x,
                const float* __restrict__ w,
                const float* __restrict__ q,
                float*       __restrict__ out,
                int n_out)
{
    extern __shared__ char smem[];
    const uint32_t sb  = smem_u32(smem);
    const uint32_t mb0 = sb;                         // NS mbarriers at [0, 32)
    float* buf = reinterpret_cast<float*>(smem + 128);

    const int tid = threadIdx.x;

    if (tid == 0) {
#pragma unroll
        for (int i = 0; i < NS; ++i) mbar_init(mb0 + 8 * i, 1);
        asm volatile("fence.proxy.async.shared::cta;" ::: "memory");
    }
    __syncthreads();

    const int ntiles = (n_out + TILE - 1) / TILE;
    int t = blockIdx.x;
    if (t >= ntiles) return;
    const int G = gridDim.x;

    auto issue = [&](int st, int tile) {
        const int cnt     = min(TILE, n_out - tile * TILE);
        const uint32_t nb = (uint32_t)cnt * SEG * 4;     // multiple of 16 here
        const uint32_t mb = mb0 + st * 8;
        const uint32_t dw = sb + 128 + st * STAGE_BYTES;
        const size_t  off = (size_t)tile * TILE_BYTES;
        mbar_expect_tx(mb, 2 * nb);
        bulk_g2s(dw,              (const char*)w + off, nb, mb);
        bulk_g2s(dw + TILE_BYTES, (const char*)q + off, nb, mb);
    };

    // Prefill stages 0..NS-2
    if (tid == 0) {
#pragma unroll
        for (int i = 0; i < NS - 1; ++i) {
            const int ti = t + i * G;
            if (ti < ntiles) issue(i, ti);
        }
    }

    const float INV_PI = 0.31830988618379067f;
    const float LN2    = 0.69314718055994531f;

    for (int j = 0; t < ntiles; ++j, t += G) {
        const int s = j & (NS - 1);

        // Refill the stage freed at the end of the previous iteration.
        if (tid == 0) {
            const int tn = t + (NS - 1) * G;
            if (tn < ntiles) issue((s + NS - 1) & (NS - 1), tn);
        }

        mbar_wait(mb0 + s * 8, (uint32_t)(j >> 2) & 1u);

        const int o = t * TILE + tid;
        if (o < n_out) {
            const int sp = o / 25;
            const int c  = sp / (OUTD * OUTD);
            const int r  = sp - c * (OUTD * OUTD);
            const int oy = r / OUTD;
            const int ox = r - oy * OUTD;

            const float* __restrict__ xp = x + (c * IMG + oy) * IMG + ox;
            float pv[SEG];
#pragma unroll
            for (int i = 0; i < SIDE; ++i)
#pragma unroll
                for (int jj = 0; jj < SIDE; ++jj)
                    pv[i * SIDE + jj] = __ldg(xp + i * IMG + jj);

            const float* wr = buf + s * (STAGE_BYTES / 4) + tid * SEG;
            const float* qr = wr + TILE_BYTES / 4;

            // 4 independent product chains to break the serial FMUL dependency.
            float pr0 = 1.0f, pr1 = 1.0f, pr2 = 1.0f, pr3 = 1.0f;
#pragma unroll
            for (int k = 0; k < SEG; ++k) {
                float tt = __fmaf_rn(pv[k], wr[k], -qr[k]);
                float a  = fast_atan(10.0f * tt);
                float v  = __fmaf_rn(a, INV_PI, 1.1f);
                if      ((k & 3) == 0) pr0 *= v;
                else if ((k & 3) == 1) pr1 *= v;
                else if ((k & 3) == 2) pr2 *= v;
                else                   pr3 *= v;
            }
            float prod = (pr0 * pr1) * (pr2 * pr3);
            out[o] = __log2f(prod) * LN2;
        }
        __syncthreads();   // stage s fully consumed -> refillable next iteration
    }
}

extern "C" void kernel_launch(void* const* d_in, const int* in_sizes, int n_in,
                              void* d_out, int out_size)
{
    const float* x = (const float*)d_in[0];
    const float* w = (const float*)d_in[1];
    const float* q = (const float*)d_in[2];
    float* out = (float*)d_out;

    cudaFuncSetAttribute(dendrite_kernel,
                         cudaFuncAttributeMaxDynamicSharedMemorySize, SMEM_BYTES);

    int sm = 148;
    cudaDeviceGetAttribute(&sm, cudaDevAttrMultiProcessorCount, 0);

    const int n_out  = out_size;                     // 1,153,200
    const int ntiles = (n_out + TILE - 1) / TILE;    // 9010
    int grid = sm * 2;
    if (grid > ntiles) grid = ntiles;

    dendrite_kernel<<<grid, TPB, SMEM_BYTES>>>(x, w, q, out, n_out);
}

// round 4
// speedup vs baseline: 1.1489x; 1.1489x over previous
#include <cuda_runtime.h>
#include <cstdint>

// Dendrite_755914244697 — persistent double-buffered cp.async.bulk pipeline,
// 4 CTAs/SM x 128 threads (16 warps/SM) to hide MUFU/LDS/LDG latency.
// out[o] = log( prod_{k<25} (1.1 + atan(10*(p[k]*w[o*25+k] - q[o*25+k]))/pi) )

#define IMG   128
#define OUTD  124
#define SIDE  5
#define SEG   25
#define TPB   128
#define TILE  128
#define NS    2
#define TILE_BYTES  (TILE * SEG * 4)           // 12800 B per array per tile
#define STAGE_BYTES (2 * TILE_BYTES)           // w + q = 25600 B
#define SMEM_BYTES  (256 + NS * STAGE_BYTES)   // 51456 B per CTA

__device__ __forceinline__ uint32_t smem_u32(const void* p)
{
    uint32_t a;
    asm("{ .reg .u64 t; cvta.to.shared.u64 t, %1; cvt.u32.u64 %0, t; }"
        : "=r"(a) : "l"(p));
    return a;
}

__device__ __forceinline__ void mbar_init(uint32_t mb, uint32_t count)
{
    asm volatile("mbarrier.init.shared.b64 [%0], %1;" :: "r"(mb), "r"(count) : "memory");
}

__device__ __forceinline__ void mbar_expect_tx(uint32_t mb, uint32_t bytes)
{
    asm volatile("mbarrier.arrive.expect_tx.shared.b64 _, [%0], %1;"
                 :: "r"(mb), "r"(bytes) : "memory");
}

__device__ __forceinline__ void bulk_g2s(uint32_t dst, const void* src,
                                         uint32_t bytes, uint32_t mb)
{
    asm volatile("cp.async.bulk.shared::cta.global.mbarrier::complete_tx::bytes "
                 "[%0], [%1], %2, [%3];"
                 :: "r"(dst), "l"(src), "r"(bytes), "r"(mb) : "memory");
}

__device__ __forceinline__ void mbar_wait(uint32_t mb, uint32_t phase)
{
    uint32_t done;
    asm volatile(
        "{ .reg .pred p;\n"
        "  mbarrier.try_wait.parity.acquire.cta.shared::cta.b64 p, [%1], %2;\n"
        "  selp.b32 %0, 1, 0, p; }"
        : "=r"(done) : "r"(mb), "r"(phase) : "memory");
    while (!done) {
        asm volatile(
            "{ .reg .pred p;\n"
            "  mbarrier.try_wait.parity.acquire.cta.shared::cta.b64 p, [%1], %2, 0x989680;\n"
            "  selp.b32 %0, 1, 0, p; }"
            : "=r"(done) : "r"(mb), "r"(phase) : "memory");
    }
}

// Signed-z atan: odd poly carries the sign; |u|>1 via atan(u)=copysign(pi/2,u)-atan(1/u).
__device__ __forceinline__ float fast_atan(float u)
{
    float inv;
    asm("rcp.approx.f32 %0, %1;" : "=f"(inv) : "f"(u));   // signed reciprocal
    bool  big = fabsf(u) > 1.0f;
    float z   = big ? inv : u;                             // signed arg, |z|<=1
    float s   = z * z;
    float p   =              -0.0040540580f;
    p = __fmaf_rn(p, s,  0.0218612288f);
    p = __fmaf_rn(p, s, -0.0559098861f);
    p = __fmaf_rn(p, s,  0.0964200441f);
    p = __fmaf_rn(p, s, -0.1390853351f);
    p = __fmaf_rn(p, s,  0.1994653599f);
    p = __fmaf_rn(p, s, -0.3332985605f);
    p = __fmaf_rn(p, s,  0.9999993329f);
    float r = p * z;                                       // sign-correct
    float c = __uint_as_float(0x3fc90fdbu |                // copysign(pi/2, u)
                              (__float_as_uint(u) & 0x80000000u));
    return big ? (c - r) : r;
}

__global__ void __launch_bounds__(TPB, 4)
dendrite_kernel(const float* __restrict__ x,
                const float* __restrict__ w,
                const float* __restrict__ q,
                float*       __restrict__ out,
                int n_out)
{
    extern __shared__ char smem[];
    const uint32_t sb  = smem_u32(smem);
    const uint32_t mb0 = sb;                       // NS mbarriers at [0, 16)
    float* buf = reinterpret_cast<float*>(smem + 256);

    const int tid = threadIdx.x;

    if (tid == 0) {
#pragma unroll
        for (int i = 0; i < NS; ++i) mbar_init(mb0 + 8 * i, 1);
        asm volatile("fence.proxy.async.shared::cta;" ::: "memory");
    }
    __syncthreads();

    const int ntiles = (n_out + TILE - 1) / TILE;
    int t = blockIdx.x;
    if (t >= ntiles) return;
    const int G = gridDim.x;

    auto issue = [&](int st, int tile) {
        const int cnt     = min(TILE, n_out - tile * TILE);
        const uint32_t nb = (uint32_t)cnt * SEG * 4;     // multiple of 16 here
        const uint32_t mb = mb0 + st * 8;
        const uint32_t dw = sb + 256 + st * STAGE_BYTES;
        const size_t  off = (size_t)tile * TILE_BYTES;
        mbar_expect_tx(mb, 2 * nb);
        bulk_g2s(dw,              (const char*)w + off, nb, mb);
        bulk_g2s(dw + TILE_BYTES, (const char*)q + off, nb, mb);
    };

    if (tid == 0) issue(0, t);     // prefill stage 0

    const float INV_PI = 0.31830988618379067f;
    const float LN2    = 0.69314718055994531f;

    for (int j = 0; t < ntiles; ++j, t += G) {
        const int s = j & 1;

        // Refill the other stage (freed by last iteration's __syncthreads).
        if (tid == 0) {
            const int tn = t + G;
            if (tn < ntiles) issue(s ^ 1, tn);
        }

        // ---- Work that doesn't depend on staged data: hide under the copy ----
        const int o = t * TILE + tid;
        float pv[SEG];
        bool active = (o < n_out);
        if (active) {
            const int sp = o / 25;
            const int c  = sp / (OUTD * OUTD);
            const int r  = sp - c * (OUTD * OUTD);
            const int oy = r / OUTD;
            const int ox = r - oy * OUTD;
            const float* __restrict__ xp = x + (c * IMG + oy) * IMG + ox;
#pragma unroll
            for (int i = 0; i < SIDE; ++i)
#pragma unroll
                for (int jj = 0; jj < SIDE; ++jj)
                    pv[i * SIDE + jj] = __ldg(xp + i * IMG + jj);
        }

        mbar_wait(mb0 + s * 8, (uint32_t)(j >> 1) & 1u);

        if (active) {
            const float* wr = buf + s * (STAGE_BYTES / 4) + tid * SEG;
            const float* qr = wr + TILE_BYTES / 4;

            // 4 independent product chains to break the serial FMUL dependency.
            float pr0 = 1.0f, pr1 = 1.0f, pr2 = 1.0f, pr3 = 1.0f;
#pragma unroll
            for (int k = 0; k < SEG; ++k) {
                float tt = __fmaf_rn(pv[k], wr[k], -qr[k]);
                float a  = fast_atan(10.0f * tt);
                float v  = __fmaf_rn(a, INV_PI, 1.1f);
                if      ((k & 3) == 0) pr0 *= v;
                else if ((k & 3) == 1) pr1 *= v;
                else if ((k & 3) == 2) pr2 *= v;
                else                   pr3 *= v;
            }
            float prod = (pr0 * pr1) * (pr2 * pr3);
            out[o] = __log2f(prod) * LN2;
        }
        __syncthreads();   // stage s fully consumed -> refillable next iteration
    }
}

extern "C" void kernel_launch(void* const* d_in, const int* in_sizes, int n_in,
                              void* d_out, int out_size)
{
    const float* x = (const float*)d_in[0];
    const float* w = (const float*)d_in[1];
    const float* q = (const float*)d_in[2];
    float* out = (float*)d_out;

    cudaFuncSetAttribute(dendrite_kernel,
                         cudaFuncAttributeMaxDynamicSharedMemorySize, SMEM_BYTES);

    int sm = 148;
    cudaDeviceGetAttribute(&sm, cudaDevAttrMultiProcessorCount, 0);

    const int n_out  = out_size;                     // 1,153,200
    const int ntiles = (n_out + TILE - 1) / TILE;    // 9010
    int grid = sm * 4;
    if (grid > ntiles) grid = ntiles;

    dendrite_kernel<<<grid, TPB, SMEM_BYTES>>>(x, w, q, out, n_out);
}